// round 8
// baseline (speedup 1.0000x reference)
#include <cuda_runtime.h>
#include <cstdint>

#define NB  32
#define NC  192
#define NL  4096
#define VPB 8                       // channels per gather block
#define NCB (NC / VPB)              // 24 channel-groups per batch
#define GBLK (NB * NCB)             // 768 gather blocks
#define GTHR 256                    // gather threads per block

// Scratch (no dynamic allocation allowed)
__device__ int   g_order[NB * NL];
__device__ int   g_count[NB];
__device__ float g_theta[NB];

__device__ __forceinline__ void pdl_trigger() {
    asm volatile("griddepcontrol.launch_dependents;" ::: "memory");
}
__device__ __forceinline__ void pdl_wait() {
    asm volatile("griddepcontrol.wait;" ::: "memory");
}
__device__ __forceinline__ uint32_t smem_u32(const void* p) {
    uint32_t a;
    asm("{ .reg .u64 t; cvta.to.shared.u64 t, %1; cvt.u32.u64 %0, t; }" : "=r"(a) : "l"(p));
    return a;
}
__device__ __forceinline__ void mbar_init(uint32_t mbar, uint32_t count) {
    asm volatile("mbarrier.init.shared.b64 [%0], %1;" :: "r"(mbar), "r"(count) : "memory");
}
__device__ __forceinline__ void mbar_expect_tx(uint32_t mbar, uint32_t bytes) {
    asm volatile("mbarrier.arrive.expect_tx.shared.b64 _, [%0], %1;" :: "r"(mbar), "r"(bytes) : "memory");
}
__device__ __forceinline__ void bulk_g2s(uint32_t dst_smem, const void* src,
                                         uint32_t bytes, uint32_t mbar) {
    asm volatile(
        "cp.async.bulk.shared::cluster.global.mbarrier::complete_tx::bytes [%0], [%1], %2, [%3];"
        :: "r"(dst_smem), "l"(src), "r"(bytes), "r"(mbar) : "memory");
}
__device__ __forceinline__ void mbar_wait(uint32_t mbar, uint32_t parity) {
    asm volatile(
        "{\n\t"
        ".reg .pred P;\n\t"
        "WAIT_%=:\n\t"
        "mbarrier.try_wait.parity.acquire.cta.shared::cta.b64 P, [%0], %1, 0x989680;\n\t"
        "@P bra DONE_%=;\n\t"
        "bra WAIT_%=;\n\t"
        "DONE_%=:\n\t"
        "}"
        :: "r"(mbar), "r"(parity) : "memory");
}

// ---------------------------------------------------------------------------
// Kernel 1: per-batch single-pass stats + stable compaction index build.
// 32 blocks x 256 threads, 16 contiguous elements per thread.
// ---------------------------------------------------------------------------
__global__ __launch_bounds__(256) void stats_scan_kernel(const float* __restrict__ delta)
{
    pdl_trigger();   // let the gather kernel start its bulk staging immediately

    const int b    = blockIdx.x;
    const int tid  = threadIdx.x;
    const int lane = tid & 31;
    const int warp = tid >> 5;   // 8 warps

    __shared__ float  smn[8], smx[8];
    __shared__ double ssum[8], ssq[8];
    __shared__ int    wsum[8];
    __shared__ float  s_lo, s_rng, s_theta;

    const float4* dp = reinterpret_cast<const float4*>(delta + (size_t)b * NL) + tid * 4;
    float a[16];
    #pragma unroll
    for (int i = 0; i < 4; i++) {
        float4 v = dp[i];
        a[4*i+0] = fabsf(v.x); a[4*i+1] = fabsf(v.y);
        a[4*i+2] = fabsf(v.z); a[4*i+3] = fabsf(v.w);
    }

    float mn = a[0], mx = a[0];
    double s = 0.0, q = 0.0;
    #pragma unroll
    for (int i = 0; i < 16; i++) {
        mn = fminf(mn, a[i]); mx = fmaxf(mx, a[i]);
        double d = (double)a[i];
        s += d; q += d * d;
    }

    #pragma unroll
    for (int o = 16; o; o >>= 1) {
        mn = fminf(mn, __shfl_xor_sync(0xffffffffu, mn, o));
        mx = fmaxf(mx, __shfl_xor_sync(0xffffffffu, mx, o));
        s += __shfl_xor_sync(0xffffffffu, s, o);
        q += __shfl_xor_sync(0xffffffffu, q, o);
    }
    if (lane == 0) { smn[warp] = mn; smx[warp] = mx; ssum[warp] = s; ssq[warp] = q; }
    __syncthreads();

    if (warp == 0 && lane < 8) {
        mn = smn[lane]; mx = smx[lane]; s = ssum[lane]; q = ssq[lane];
        #pragma unroll
        for (int o = 4; o; o >>= 1) {
            mn = fminf(mn, __shfl_xor_sync(0xffu, mn, o));
            mx = fmaxf(mx, __shfl_xor_sync(0xffu, mx, o));
            s += __shfl_xor_sync(0xffu, s, o);
            q += __shfl_xor_sync(0xffu, q, o);
        }
        if (lane == 0) {
            float lo  = mn;
            float rng = fmaxf(mx - lo, 1e-3f);
            double mu_a  = s / (double)NL;
            double var_a = (q - s * s / (double)NL) / (double)(NL - 1);
            if (var_a < 0.0) var_a = 0.0;
            double mu_imp = (mu_a - (double)lo) / (double)rng;
            double sg_imp = sqrt(var_a) / (double)rng;
            s_lo = lo; s_rng = rng;
            s_theta = (float)(mu_imp - 0.1 * sg_imp);
        }
    }
    __syncthreads();

    const float lo = s_lo, rng = s_rng, theta = s_theta;

    unsigned kbits = 0;
    int local = 0;
    #pragma unroll
    for (int i = 0; i < 16; i++) {
        float imp = (a[i] - lo) / rng;
        if (imp >= theta) { kbits |= (1u << i); local++; }
    }

    int incl = local;
    #pragma unroll
    for (int o = 1; o < 32; o <<= 1) {
        int t = __shfl_up_sync(0xffffffffu, incl, o);
        if (lane >= o) incl += t;
    }
    if (lane == 31) wsum[warp] = incl;
    __syncthreads();
    if (warp == 0 && lane < 8) {
        int t = wsum[lane];
        #pragma unroll
        for (int o = 1; o < 8; o <<= 1) {
            int u = __shfl_up_sync(0xffu, t, o);
            if (lane >= o) t += u;
        }
        wsum[lane] = t;
    }
    __syncthreads();

    int pos  = (warp ? wsum[warp - 1] : 0) + (incl - local);
    int base = b * NL;
    int l    = tid * 16;
    #pragma unroll
    for (int i = 0; i < 16; i++) {
        if (kbits & (1u << i)) g_order[base + pos++] = l + i;
    }

    int cnt_total = wsum[7];
    for (int j = cnt_total + tid; j < NL; j += 256) g_order[base + j] = 0;

    if (tid == 0) {
        g_count[b] = cnt_total;
        g_theta[b] = theta;
    }
}

// ---------------------------------------------------------------------------
// Kernel 2: pipelined gather. One block per (b, 8 channels); 256 threads.
// x channels streamed via double-buffered cp.async.bulk + mbarrier so the
// DRAM read stream overlaps the SMEM-gather/store phase continuously.
// Order indices loaded to registers once, reused for all 8 channels.
// ---------------------------------------------------------------------------
__global__ __launch_bounds__(GTHR) void gather_kernel(const float* __restrict__ x,
                                                      float* __restrict__ y,
                                                      float* __restrict__ out_kr,
                                                      float* __restrict__ out_tm)
{
    __shared__ float sx[2][NL];                       // 2 x 16 KB
    __shared__ __align__(8) unsigned long long mbar_sto[2];

    const int blk = blockIdx.x;
    const int tid = threadIdx.x;
    const int b   = blk / NCB;
    const int c0  = (blk % NCB) * VPB;
    const size_t base = ((size_t)b * NC + c0) * NL;

    const uint32_t mb0 = smem_u32(&mbar_sto[0]);
    const uint32_t mb1 = smem_u32(&mbar_sto[1]);
    const uint32_t sx0 = smem_u32(&sx[0][0]);
    const uint32_t sx1 = smem_u32(&sx[1][0]);

    if (tid == 0) { mbar_init(mb0, 1); mbar_init(mb1, 1); }
    __syncthreads();

    // Prologue: start streaming channels 0 and 1 (independent of stats).
    if (tid == 0) {
        mbar_expect_tx(mb0, NL * 4);
        bulk_g2s(sx0, x + base, NL * 4, mb0);
        mbar_expect_tx(mb1, NL * 4);
        bulk_g2s(sx1, x + base + NL, NL * 4, mb1);
    }

    // Wait for stats kernel completion, then fetch order once.
    pdl_wait();
    const int4* op = reinterpret_cast<const int4*>(g_order + b * NL) + 4 * tid;
    int4 o[4];
    #pragma unroll
    for (int i = 0; i < 4; i++) o[i] = op[i];
    const int cnt = g_count[b];
    const int j0  = tid * 16;

    #pragma unroll
    for (int v = 0; v < VPB; v++) {
        const int s = v & 1;
        const uint32_t mb = s ? mb1 : mb0;
        const float* sr = sx[s];

        mbar_wait(mb, (v >> 1) & 1);

        float4* yp = reinterpret_cast<float4*>(y + base + (size_t)v * NL) + 4 * tid;
        #pragma unroll
        for (int i = 0; i < 4; i++) {
            const int j = j0 + 4 * i;
            float4 r;
            r.x = (j     < cnt) ? sr[o[i].x] : 0.0f;
            r.y = (j + 1 < cnt) ? sr[o[i].y] : 0.0f;
            r.z = (j + 2 < cnt) ? sr[o[i].z] : 0.0f;
            r.w = (j + 3 < cnt) ? sr[o[i].w] : 0.0f;
            yp[i] = r;
        }

        __syncthreads();   // all reads of sx[s] complete before refill

        if (v + 2 < VPB && tid == 0) {
            mbar_expect_tx(mb, NL * 4);
            bulk_g2s(s ? sx1 : sx0, x + base + (size_t)(v + 2) * NL, NL * 4, mb);
        }
    }

    // scalar outputs
    if (blk == 0 && tid < 32) {
        float cntf = (float)g_count[tid];
        float th   = g_theta[tid];
        #pragma unroll
        for (int o2 = 16; o2; o2 >>= 1) {
            cntf += __shfl_xor_sync(0xffffffffu, cntf, o2);
            th   += __shfl_xor_sync(0xffffffffu, th,   o2);
        }
        if (tid == 0) {
            *out_kr = (cntf / (float)NB) / (float)NL;
            *out_tm = th / (float)NB;
        }
    }
}

extern "C" void kernel_launch(void* const* d_in, const int* in_sizes, int n_in,
                              void* d_out, int out_size)
{
    const float* x     = (const float*)d_in[0];   // [32,192,64,64]
    const float* delta = (const float*)d_in[1];   // [32,1,64,64]
    float* out = (float*)d_out;

    stats_scan_kernel<<<NB, 256>>>(delta);

    cudaLaunchConfig_t cfg = {};
    cfg.gridDim  = dim3(GBLK, 1, 1);
    cfg.blockDim = dim3(GTHR, 1, 1);
    cfg.dynamicSmemBytes = 0;
    cfg.stream = 0;
    cudaLaunchAttribute attr[1];
    attr[0].id = cudaLaunchAttributeProgrammaticStreamSerialization;
    attr[0].val.programmaticStreamSerializationAllowed = 1;
    cfg.attrs = attr;
    cfg.numAttrs = 1;
    cudaLaunchKernelEx(&cfg, gather_kernel, x, out,
                       out + (out_size - 2), out + (out_size - 1));
}